// round 4
// baseline (speedup 1.0000x reference)
#include <cuda_runtime.h>
#include <cstdint>

// ---------------------------------------------------------------------------
// FidelityLSTM: 2-layer LSTM (B=256, T=256, I=512, H=1024) + linear readout.
//
// Round-3 changes vs round-2:
//  * Weights pre-packed in GLOBAL memory in mma-fragment order -> B operand
//    smem fill is a contiguous cp.async.cg copy; B fragment read = 1x LDS.64.
//  * A tile written to smem in fragment order -> A fragment read = 1x LDS.128.
//  * Double-buffered k-panel pipeline (cp.async for B, reg-staged tf32-rounded
//    A), overlapping fills with mma compute.
//  * Everything else (gate-interleaved layout, fused cell epilogue, tf32
//    mma.sync m16n8k8 with cvt.rna rounding) unchanged.
// ---------------------------------------------------------------------------

#define BB   256
#define TT   256
#define II   512
#define HH   1024
#define G4H  4096   // 4*H
#define N8TOT 512   // G4H / 8

// ------------------------- scratch (device globals) ------------------------
__device__ float g_xg[(size_t)BB * TT * G4H];    // precomputed input gates
__device__ float g_hall[(size_t)BB * TT * HH];   // layer-0 hidden sequence
__device__ float g_h[2][BB * HH];                // ping-pong hidden state
__device__ float g_c[BB * HH];                   // cell state
__device__ float g_Wih0p[G4H * II];              // packed (fragment-major)
__device__ float g_Whh0p[G4H * HH];
__device__ float g_Wih1p[G4H * HH];
__device__ float g_Whh1p[G4H * HH];
__device__ float g_b0p[G4H];
__device__ float g_b1p[G4H];

// ------------------------------ helpers ------------------------------------
__device__ __forceinline__ uint32_t tf32u(float x) {
    uint32_t u;
    asm("cvt.rna.tf32.f32 %0, %1;" : "=r"(u) : "f"(x));
    return u;
}

__device__ __forceinline__ void mma_tf32(float d[4], const uint32_t a[4],
                                         const uint32_t b[2]) {
    asm("mma.sync.aligned.m16n8k8.row.col.f32.tf32.tf32.f32 "
        "{%0,%1,%2,%3}, {%4,%5,%6,%7}, {%8,%9}, {%0,%1,%2,%3};"
        : "+f"(d[0]), "+f"(d[1]), "+f"(d[2]), "+f"(d[3])
        : "r"(a[0]), "r"(a[1]), "r"(a[2]), "r"(a[3]), "r"(b[0]), "r"(b[1]));
}

__device__ __forceinline__ float sigmoidf_(float x) {
    return 1.f / (1.f + __expf(-x));
}

__device__ __forceinline__ void cpa16(float* dst_smem, const float* src) {
    uint32_t d = (uint32_t)__cvta_generic_to_shared(dst_smem);
    asm volatile("cp.async.cg.shared.global [%0], [%1], 16;\n"
                 :: "r"(d), "l"(src));
}

// ---------------------------------------------------------------------------
// Fragment-major smem layouts (k-panel of 32):
//   A (64 rows): As[m16][ks][lane][4]   m16 = row/16, pos = (khalf)*2+(row>>3&1)
//   B (128 n):   Bs[n8][ks][lane][2]    n8 = n/8,     pair = k-halves
// Packed global W: blocks of 256 floats indexed by (kp*N8TOT + n8).
// ---------------------------------------------------------------------------
__device__ __forceinline__ void fillA(const float* __restrict__ A, int m0,
                                      int K, int k0, float* As) {
    const int tid = threadIdx.x;
    #pragma unroll
    for (int i = 0; i < 2; i++) {
        int idx = tid + i * 256;               // 0..511
        int r   = idx >> 3;                    // 0..63
        int c4  = (idx & 7) << 2;              // 0,4,...,28
        float4 v = *(const float4*)(A + (size_t)(m0 + r) * K + k0 + c4);
        int m16 = r >> 4;
        int ks  = c4 >> 3;
        int pos = (((c4 >> 2) & 1) << 1) | ((r >> 3) & 1);
        float* b = As + (m16 * 4 + ks) * 128 + ((r & 7) << 2) * 4 + pos;
        b[0]  = __uint_as_float(tf32u(v.x));
        b[4]  = __uint_as_float(tf32u(v.y));
        b[8]  = __uint_as_float(tf32u(v.z));
        b[12] = __uint_as_float(tf32u(v.w));
    }
}

__device__ __forceinline__ void fillB(const float* __restrict__ Wp, int p0,
                                      int kp, float* Bs) {
    const float* src = Wp + ((size_t)kp * N8TOT + (p0 >> 3)) * 256;
    const int tid = threadIdx.x;
    #pragma unroll
    for (int q = 0; q < 4; q++) {
        int off = (tid + q * 256) * 4;
        cpa16(Bs + off, src + off);
    }
}

// C tile 64(m) x 128(n), 8 warps = 2(m) x 4(n), warp tile 32x32.
// smem: As0,As1 = 2048 floats each; Bs0,Bs1 = 4096 floats each (48KB total).
__device__ __forceinline__ void gemm_pipe(const float* __restrict__ A, int m0,
                                          const float* __restrict__ Wp, int p0,
                                          int K, float* smem,
                                          float acc[2][4][4])
{
    float* As0 = smem;
    float* As1 = smem + 2048;
    float* Bs0 = smem + 4096;
    float* Bs1 = smem + 8192;

    const int lane = threadIdx.x & 31;
    const int warp = threadIdx.x >> 5;
    const int wm   = warp >> 2;   // 0..1
    const int wn   = warp & 3;    // 0..3
    const int NKP  = K >> 5;

    fillA(A, m0, K, 0, As0);
    fillB(Wp, p0, 0, Bs0);
    asm volatile("cp.async.commit_group;\n");

    for (int kp = 0; kp < NKP; kp++) {
        float* Asc = (kp & 1) ? As1 : As0;
        float* Bsc = (kp & 1) ? Bs1 : Bs0;
        float* Asn = (kp & 1) ? As0 : As1;
        float* Bsn = (kp & 1) ? Bs0 : Bs1;

        if (kp + 1 < NKP) {
            fillA(A, m0, K, (kp + 1) << 5, Asn);
            fillB(Wp, p0, kp + 1, Bsn);
            asm volatile("cp.async.commit_group;\n");
            asm volatile("cp.async.wait_group 1;\n");
        } else {
            asm volatile("cp.async.wait_group 0;\n");
        }
        __syncthreads();

        #pragma unroll
        for (int ks = 0; ks < 4; ks++) {
            uint32_t a[2][4];
            #pragma unroll
            for (int mf = 0; mf < 2; mf++) {
                float4 av = *(const float4*)(Asc + ((wm * 2 + mf) * 4 + ks) * 128
                                             + lane * 4);
                a[mf][0] = __float_as_uint(av.x);
                a[mf][1] = __float_as_uint(av.y);
                a[mf][2] = __float_as_uint(av.z);
                a[mf][3] = __float_as_uint(av.w);
            }
            #pragma unroll
            for (int nf = 0; nf < 4; nf++) {
                float2 bv = *(const float2*)(Bsc + ((wn * 4 + nf) * 4 + ks) * 64
                                             + lane * 2);
                uint32_t b[2] = { __float_as_uint(bv.x), __float_as_uint(bv.y) };
                mma_tf32(acc[0][nf], a[0], b);
                mma_tf32(acc[1][nf], a[1], b);
            }
        }
        __syncthreads();
    }
}

// ---------------------------------------------------------------------------
// Input GEMM: xg[m][p] = sum_k A[m][k] * W_ih_p[p][k] + bias_p[p]
// grid: (G4H/128, (B*T)/64) = (32, 1024), 256 threads.
// ---------------------------------------------------------------------------
__global__ void __launch_bounds__(256)
input_gemm_kernel(const float* __restrict__ ctx, int layer)
{
    __shared__ __align__(16) float smem[12288];

    const float* A    = layer ? g_hall  : ctx;
    const float* Wp   = layer ? g_Wih1p : g_Wih0p;
    const float* bias = layer ? g_b1p   : g_b0p;
    const int K = layer ? HH : II;

    const int m0 = blockIdx.y * 64;
    const int p0 = blockIdx.x * 128;

    float acc[2][4][4];
    #pragma unroll
    for (int i = 0; i < 2; i++)
        #pragma unroll
        for (int j = 0; j < 4; j++)
            #pragma unroll
            for (int l = 0; l < 4; l++) acc[i][j][l] = 0.f;

    gemm_pipe(A, m0, Wp, p0, K, smem, acc);

    const int lane = threadIdx.x & 31;
    const int warp = threadIdx.x >> 5;
    const int wm = warp >> 2, wn = warp & 3;

    #pragma unroll
    for (int mf = 0; mf < 2; mf++) {
        int gm = m0 + wm * 32 + mf * 16 + (lane >> 2);
        #pragma unroll
        for (int nf = 0; nf < 4; nf++) {
            int gp = p0 + wn * 32 + nf * 8 + ((lane & 3) << 1);
            float b0v = bias[gp], b1v = bias[gp + 1];
            size_t base = (size_t)gm * G4H + gp;
            g_xg[base]     = acc[mf][nf][0] + b0v;
            g_xg[base + 1] = acc[mf][nf][1] + b1v;
            size_t base2 = base + (size_t)8 * G4H;
            g_xg[base2]     = acc[mf][nf][2] + b0v;
            g_xg[base2 + 1] = acc[mf][nf][3] + b1v;
        }
    }
}

// ---------------------------------------------------------------------------
// LSTM step: gates = xg[:,t,:] + h_in @ W_hh_p^T, fused cell update.
// grid: (32, 4), 256 threads.
// ---------------------------------------------------------------------------
template <bool STORE_SEQ>
__global__ void __launch_bounds__(256)
lstm_step_kernel(int layer, int t, int hin)
{
    __shared__ __align__(16) float smem[12288];

    const float* Wp   = layer ? g_Whh1p : g_Whh0p;
    const float* A    = g_h[hin];
    float*       hout = g_h[hin ^ 1];

    const int m0 = blockIdx.y * 64;
    const int p0 = blockIdx.x * 128;

    float acc[2][4][4];
    #pragma unroll
    for (int i = 0; i < 2; i++)
        #pragma unroll
        for (int j = 0; j < 4; j++)
            #pragma unroll
            for (int l = 0; l < 4; l++) acc[i][j][l] = 0.f;

    gemm_pipe(A, m0, Wp, p0, HH, smem, acc);

    const int lane = threadIdx.x & 31;
    const int warp = threadIdx.x >> 5;
    const int wm = warp >> 2, wn = warp & 3;

    // stage gates (+ xg) into smem so each thread can gather i,f,g,o per unit
    float* gs = smem;  // [64][132] = 8448 floats
    #pragma unroll
    for (int mf = 0; mf < 2; mf++) {
        int lm = wm * 32 + mf * 16 + (lane >> 2);
        int gb = m0 + lm;
        #pragma unroll
        for (int nf = 0; nf < 4; nf++) {
            int lp = wn * 32 + nf * 8 + ((lane & 3) << 1);
            size_t x0 = ((size_t)gb * TT + t) * G4H + p0 + lp;
            gs[lm * 132 + lp]     = acc[mf][nf][0] + g_xg[x0];
            gs[lm * 132 + lp + 1] = acc[mf][nf][1] + g_xg[x0 + 1];
            size_t x1 = ((size_t)(gb + 8) * TT + t) * G4H + p0 + lp;
            gs[(lm + 8) * 132 + lp]     = acc[mf][nf][2] + g_xg[x1];
            gs[(lm + 8) * 132 + lp + 1] = acc[mf][nf][3] + g_xg[x1 + 1];
        }
    }
    __syncthreads();

    const int j0 = p0 >> 2;  // first hidden unit of this tile
    #pragma unroll
    for (int it = threadIdx.x; it < 64 * 32; it += 256) {
        int lm = it >> 5;
        int lj = it & 31;
        float4 gv = *(float4*)(gs + lm * 132 + (lj << 2));
        int b = m0 + lm;
        int j = j0 + lj;
        float ig = sigmoidf_(gv.x);
        float fg = sigmoidf_(gv.y);
        float gg = tanhf(gv.z);
        float og = sigmoidf_(gv.w);
        int hc = b * HH + j;
        float c = fg * g_c[hc] + ig * gg;
        g_c[hc] = c;
        float h = og * tanhf(c);
        hout[hc] = h;
        if (STORE_SEQ)
            g_hall[((size_t)b * TT + t) * HH + j] = h;
    }
}

// ---------------------------------------------------------------------------
// Weight permutation into packed fragment-major layout (+ tf32 rounding).
// Output flat index decomposition:
//   half=idx&1, lane=(idx>>1)&31, ks=(idx>>6)&3, n8=(idx>>8)&511, kp=idx>>17
//   p = n8*8 + (lane>>2)           (gate-interleaved p = 4j+g)
//   k = kp*32 + ks*8 + (lane&3) + half*4
// ---------------------------------------------------------------------------
__global__ void permute_kernel(const float* __restrict__ src, int sel, int K)
{
    float* dst = (sel == 0) ? g_Wih0p : (sel == 1) ? g_Whh0p
               : (sel == 2) ? g_Wih1p : g_Whh1p;
    size_t n = (size_t)G4H * K;
    for (size_t idx = (size_t)blockIdx.x * blockDim.x + threadIdx.x; idx < n;
         idx += (size_t)gridDim.x * blockDim.x) {
        int half = (int)(idx & 1);
        int lane = (int)((idx >> 1) & 31);
        int ks   = (int)((idx >> 6) & 3);
        size_t rest = idx >> 8;
        int n8 = (int)(rest & (N8TOT - 1));
        int kp = (int)(rest >> 9);
        int p = n8 * 8 + (lane >> 2);
        int k = kp * 32 + ks * 8 + (lane & 3) + half * 4;
        int j = p >> 2, g = p & 3;
        dst[idx] = __uint_as_float(tf32u(src[(size_t)(g * HH + j) * K + k]));
    }
}

__global__ void bias_kernel(const float* __restrict__ bih,
                            const float* __restrict__ bhh, int layer)
{
    int p = blockIdx.x * blockDim.x + threadIdx.x;
    if (p < G4H) {
        int j = p >> 2, g = p & 3;
        int r = g * HH + j;
        (layer ? g_b1p : g_b0p)[p] = bih[r] + bhh[r];
    }
}

__global__ void init_hc_kernel(const float* __restrict__ init_hidden)
{
    int i = blockIdx.x * blockDim.x + threadIdx.x;
    if (i < BB * HH) {
        g_h[0][i] = init_hidden[i];
        g_c[i] = 0.f;
    }
}

__global__ void readout_kernel(const float* __restrict__ Wro,
                               const float* __restrict__ bro,
                               float* __restrict__ out)
{
    int b = blockIdx.x;
    const float* h = g_h[0] + b * HH;
    float s = 0.f;
    for (int j = threadIdx.x; j < HH; j += 128) s += h[j] * Wro[j];
    #pragma unroll
    for (int o = 16; o; o >>= 1) s += __shfl_down_sync(0xffffffff, s, o);
    __shared__ float red[4];
    if ((threadIdx.x & 31) == 0) red[threadIdx.x >> 5] = s;
    __syncthreads();
    if (threadIdx.x == 0)
        out[b] = red[0] + red[1] + red[2] + red[3] + bro[0];
}

// ---------------------------------------------------------------------------
extern "C" void kernel_launch(void* const* d_in, const int* in_sizes, int n_in,
                              void* d_out, int out_size)
{
    const float* init_hidden = (const float*)d_in[0];
    const float* context     = (const float*)d_in[1];
    const float* W_ih0       = (const float*)d_in[2];
    const float* W_hh0       = (const float*)d_in[3];
    const float* b_ih0       = (const float*)d_in[4];
    const float* b_hh0       = (const float*)d_in[5];
    const float* W_ih1       = (const float*)d_in[6];
    const float* W_hh1       = (const float*)d_in[7];
    const float* b_ih1       = (const float*)d_in[8];
    const float* b_hh1       = (const float*)d_in[9];
    const float* W_ro        = (const float*)d_in[10];
    const float* b_ro        = (const float*)d_in[11];
    float* out = (float*)d_out;

    // weight/bias preprocessing (tf32-rounded, fragment-major packed)
    permute_kernel<<<2048, 256>>>(W_ih0, 0, II);
    permute_kernel<<<2048, 256>>>(W_hh0, 1, HH);
    permute_kernel<<<2048, 256>>>(W_ih1, 2, HH);
    permute_kernel<<<2048, 256>>>(W_hh1, 3, HH);
    bias_kernel<<<(G4H + 255) / 256, 256>>>(b_ih0, b_hh0, 0);
    bias_kernel<<<(G4H + 255) / 256, 256>>>(b_ih1, b_hh1, 1);

    const dim3 blk(256);
    const dim3 g_in(G4H / 128, (BB * TT) / 64);  // (32, 1024)
    const dim3 g_st(G4H / 128, BB / 64);         // (32, 4)
    const int  ginit = (BB * HH + 255) / 256;

    // ---- layer 0 ----
    input_gemm_kernel<<<g_in, blk>>>(context, 0);
    init_hc_kernel<<<ginit, 256>>>(init_hidden);
    for (int t = 0; t < TT; t++)
        lstm_step_kernel<true><<<g_st, blk>>>(0, t, t & 1);

    // ---- layer 1 ----
    input_gemm_kernel<<<g_in, blk>>>(nullptr, 1);
    init_hc_kernel<<<ginit, 256>>>(init_hidden);
    for (int t = 0; t < TT; t++)
        lstm_step_kernel<false><<<g_st, blk>>>(1, t, t & 1);

    // ---- readout ----
    readout_kernel<<<BB, 128>>>(W_ro, b_ro, out);
}

// round 7
// speedup vs baseline: 2.0342x; 2.0342x over previous
#include <cuda_runtime.h>
#include <cuda_fp16.h>
#include <cstdint>

// ---------------------------------------------------------------------------
// FidelityLSTM: 2-layer LSTM (B=256, T=256, I=512, H=1024) + linear readout.
//
// Round-6: tcgen05 is unavailable (harness ptxas target is sm_100, not
// sm_100a). Round-3 (27.7ms) sat at the legacy tf32 mma.sync ceiling, so
// this round doubles the tensor rate by moving to fp16 m16n8k16 (same
// 11-bit significand as tf32 -> equivalent numerics for this value range),
// with all operands pre-packed as fp16 blocks so the mainloop is pure
// cp.async + ldmatrix + HMMA.
// ---------------------------------------------------------------------------

#define BB   256
#define TT   256
#define II   512
#define HH   1024
#define G4H  4096

// ------------------------- scratch (device globals) ------------------------
// W blocks: [128 n][32 k] halves, contiguous 4096 halves, index (nt*NKP+kp).
// A blocks: [64 rows][32 k] halves, contiguous 2048 halves, index (mt*NKP+kp).
__device__ __align__(16) __half g_Wih0p[(size_t)G4H * II];
__device__ __align__(16) __half g_Whh0p[(size_t)G4H * HH];
__device__ __align__(16) __half g_Wih1p[(size_t)G4H * HH];
__device__ __align__(16) __half g_Whh1p[(size_t)G4H * HH];
__device__ float g_b0p[G4H];
__device__ float g_b1p[G4H];
__device__ __align__(16) __half g_ctxp[(size_t)BB * TT * II];
__device__ __align__(16) __half g_hallp[(size_t)BB * TT * HH];
__device__ __align__(16) __half g_hA[2][BB * HH];
__device__ float g_c[BB * HH];
__device__ float g_xg[(size_t)BB * TT * G4H];

// ------------------------------ helpers ------------------------------------
__device__ __forceinline__ float sigmoidf_(float x) {
    return 1.f / (1.f + __expf(-x));
}

__device__ __forceinline__ void cpa16(const __half* dst, const __half* src) {
    uint32_t d = (uint32_t)__cvta_generic_to_shared(dst);
    asm volatile("cp.async.cg.shared.global [%0], [%1], 16;\n"
                 :: "r"(d), "l"(src));
}

__device__ __forceinline__ void ldsm4(uint32_t r[4], const __half* p) {
    uint32_t a = (uint32_t)__cvta_generic_to_shared(p);
    asm volatile("ldmatrix.sync.aligned.m8n8.x4.shared.b16 {%0,%1,%2,%3}, [%4];"
                 : "=r"(r[0]), "=r"(r[1]), "=r"(r[2]), "=r"(r[3]) : "r"(a));
}

__device__ __forceinline__ void mma16(float d[4], const uint32_t a[4],
                                      uint32_t b0, uint32_t b1) {
    asm volatile(
        "mma.sync.aligned.m16n8k16.row.col.f32.f16.f16.f32 "
        "{%0,%1,%2,%3}, {%4,%5,%6,%7}, {%8,%9}, {%0,%1,%2,%3};"
        : "+f"(d[0]), "+f"(d[1]), "+f"(d[2]), "+f"(d[3])
        : "r"(a[0]), "r"(a[1]), "r"(a[2]), "r"(a[3]), "r"(b0), "r"(b1));
}

// ---------------------------------------------------------------------------
// GEMM mainloop: C[64 x 128] tile, A blocks [64x32], B blocks [128x32].
// 256 threads, 8 warps = 2(m) x 4(n), warp tile 32x32, mma m16n8k16.
// smem rows padded to 40 halves (80B) -> ldmatrix conflict-free.
// smem usage: A 2x2560 + B 2x5120 = 15360 halves = 30720B.
// ---------------------------------------------------------------------------
__device__ __forceinline__ void gemm_fp16(
    const __half* __restrict__ Ablk, const __half* __restrict__ Bblk,
    int NKP, __half* sm, float acc[2][4][4])
{
    const int tid  = threadIdx.x;
    const int lane = tid & 31;
    const int warp = tid >> 5;
    const int wm   = warp >> 2;   // 0..1
    const int wn   = warp & 3;    // 0..3

    __half* As[2] = { sm,        sm + 2560 };
    __half* Bs[2] = { sm + 5120, sm + 10240 };

    const int ar = tid >> 2;            // 0..63
    const int ac = (tid & 3) * 8;       // 0,8,16,24

#define FILL_PANEL(kp, buf) do {                                            \
        const __half* ga = Ablk + (size_t)(kp) * 2048;                      \
        const __half* gb = Bblk + (size_t)(kp) * 4096;                      \
        cpa16(As[buf] + ar * 40 + ac, ga + ar * 32 + ac);                   \
        cpa16(Bs[buf] + ar * 40 + ac, gb + ar * 32 + ac);                   \
        cpa16(Bs[buf] + (ar + 64) * 40 + ac, gb + (ar + 64) * 32 + ac);     \
        asm volatile("cp.async.commit_group;\n");                           \
    } while (0)

    FILL_PANEL(0, 0);

    for (int kp = 0; kp < NKP; kp++) {
        const int cur = kp & 1;
        if (kp + 1 < NKP) {
            FILL_PANEL(kp + 1, cur ^ 1);
            asm volatile("cp.async.wait_group 1;\n");
        } else {
            asm volatile("cp.async.wait_group 0;\n");
        }
        __syncthreads();

        __half* Ac = As[cur];
        __half* Bc = Bs[cur];
        #pragma unroll
        for (int ks = 0; ks < 2; ks++) {
            uint32_t a[2][4];
            #pragma unroll
            for (int mf = 0; mf < 2; mf++) {
                int row = wm * 32 + mf * 16 + (lane & 7) + (lane & 8);
                int col = ks * 16 + ((lane >> 4) & 1) * 8;
                ldsm4(a[mf], Ac + row * 40 + col);
            }
            #pragma unroll
            for (int nfp = 0; nfp < 2; nfp++) {
                int row = wn * 32 + nfp * 16 + (lane & 7) + ((lane & 16) >> 1);
                int col = ks * 16 + (lane & 8);
                uint32_t b[4];
                ldsm4(b, Bc + row * 40 + col);
                mma16(acc[0][nfp * 2],     a[0], b[0], b[1]);
                mma16(acc[1][nfp * 2],     a[1], b[0], b[1]);
                mma16(acc[0][nfp * 2 + 1], a[0], b[2], b[3]);
                mma16(acc[1][nfp * 2 + 1], a[1], b[2], b[3]);
            }
        }
        __syncthreads();
    }
#undef FILL_PANEL
}

// ---------------------------------------------------------------------------
// Input GEMM: xg[row][p] = sum_k A[row][k] * W[p][k] + bias[p]
// grid (32, 1024) tiles of 64(m) x 128(n), 256 threads.
// ---------------------------------------------------------------------------
__global__ void __launch_bounds__(256)
input_gemm_kernel(int layer)
{
    __shared__ __align__(16) float smem_f[8448];
    __half* sm = (__half*)smem_f;

    const int NKP = layer ? (HH / 32) : (II / 32);
    const __half* Ap   = layer ? g_hallp : g_ctxp;
    const __half* Wp   = layer ? g_Wih1p : g_Wih0p;
    const float*  bias = layer ? g_b1p   : g_b0p;

    const int nt = blockIdx.x;            // p0 = nt*128
    const int mt = blockIdx.y;            // m0 = mt*64
    const int p0 = nt * 128;
    const int m0 = mt * 64;

    float acc[2][4][4];
    #pragma unroll
    for (int i = 0; i < 2; i++)
        #pragma unroll
        for (int j = 0; j < 4; j++)
            #pragma unroll
            for (int l = 0; l < 4; l++) acc[i][j][l] = 0.f;

    gemm_fp16(Ap + (size_t)mt * NKP * 2048, Wp + (size_t)nt * NKP * 4096,
              NKP, sm, acc);

    const int lane = threadIdx.x & 31;
    const int warp = threadIdx.x >> 5;
    const int wm = warp >> 2, wn = warp & 3;

    #pragma unroll
    for (int mf = 0; mf < 2; mf++) {
        int gm = m0 + wm * 32 + mf * 16 + (lane >> 2);
        #pragma unroll
        for (int nf = 0; nf < 4; nf++) {
            int gp = p0 + wn * 32 + nf * 8 + ((lane & 3) << 1);
            float b0v = bias[gp], b1v = bias[gp + 1];
            size_t base = (size_t)gm * G4H + gp;
            g_xg[base]     = acc[mf][nf][0] + b0v;
            g_xg[base + 1] = acc[mf][nf][1] + b1v;
            size_t base2 = base + (size_t)8 * G4H;
            g_xg[base2]     = acc[mf][nf][2] + b0v;
            g_xg[base2 + 1] = acc[mf][nf][3] + b1v;
        }
    }
}

// ---------------------------------------------------------------------------
// LSTM step: gates = xg[:,t,:] + h_in @ W_hh^T, fused cell update.
// grid (32, 4): nt owns gate cols [nt*128, +128) = units [nt*32, +32),
// mtl owns batch rows [mtl*64, +64). 256 threads.
// ---------------------------------------------------------------------------
template <bool STORE_SEQ>
__global__ void __launch_bounds__(256)
lstm_step_kernel(int layer, int t, int hin)
{
    __shared__ __align__(16) float smem_f[8448];
    __half* sm = (__half*)smem_f;

    const __half* Wp  = layer ? g_Whh1p : g_Whh0p;
    const __half* Ain = g_hA[hin];
    __half*      hout = g_hA[hin ^ 1];

    const int nt  = blockIdx.x;           // 0..31
    const int mtl = blockIdx.y;           // 0..3
    const int p0  = nt * 128;
    const int m0  = mtl * 64;

    float acc[2][4][4];
    #pragma unroll
    for (int i = 0; i < 2; i++)
        #pragma unroll
        for (int j = 0; j < 4; j++)
            #pragma unroll
            for (int l = 0; l < 4; l++) acc[i][j][l] = 0.f;

    gemm_fp16(Ain + (size_t)mtl * 32 * 2048, Wp + (size_t)nt * 32 * 4096,
              32, sm, acc);

    const int lane = threadIdx.x & 31;
    const int warp = threadIdx.x >> 5;
    const int wm = warp >> 2, wn = warp & 3;

    // stage gates (+ xg) into smem so each thread can gather i,f,g,o per unit
    float* gs = smem_f;   // [64][132]
    #pragma unroll
    for (int mf = 0; mf < 2; mf++) {
        int lm = wm * 32 + mf * 16 + (lane >> 2);
        int gb = m0 + lm;
        #pragma unroll
        for (int nf = 0; nf < 4; nf++) {
            int lp = wn * 32 + nf * 8 + ((lane & 3) << 1);
            size_t x0 = ((size_t)gb * TT + t) * G4H + p0 + lp;
            gs[lm * 132 + lp]     = acc[mf][nf][0] + g_xg[x0];
            gs[lm * 132 + lp + 1] = acc[mf][nf][1] + g_xg[x0 + 1];
            size_t x1 = ((size_t)(gb + 8) * TT + t) * G4H + p0 + lp;
            gs[(lm + 8) * 132 + lp]     = acc[mf][nf][2] + g_xg[x1];
            gs[(lm + 8) * 132 + lp + 1] = acc[mf][nf][3] + g_xg[x1 + 1];
        }
    }
    __syncthreads();

    const int j0 = p0 >> 2;  // first hidden unit of this tile
    #pragma unroll
    for (int it = threadIdx.x; it < 64 * 32; it += 256) {
        int lm = it >> 5;      // local batch row
        int lj = it & 31;      // local hidden unit
        float4 gv = *(float4*)(gs + lm * 132 + (lj << 2));
        int b = m0 + lm;
        int j = j0 + lj;
        float ig = sigmoidf_(gv.x);
        float fg = sigmoidf_(gv.y);
        float gg = tanhf(gv.z);
        float og = sigmoidf_(gv.w);
        int hc = b * HH + j;
        float c = fg * g_c[hc] + ig * gg;
        g_c[hc] = c;
        __half h = __float2half_rn(og * tanhf(c));
        // next-step A image: block (mtl, kp=nt), row lm, k-col lj
        hout[(size_t)(mtl * 32 + nt) * 2048 + lm * 32 + lj] = h;
        if (STORE_SEQ) {
            // layer-1 input image: global row r = b*TT+t -> block r/64,
            // row r%64 = t&63 (since TT=256 multiple of 64)
            size_t blk = (size_t)(b * 4 + (t >> 6)) * 32 + nt;
            g_hallp[blk * 2048 + (t & 63) * 32 + lj] = h;
        }
    }
}

// ---------------------------------------------------------------------------
// Packing kernels (fp32 -> fp16 RN, gate-interleaved p = 4j+g, blocked)
// ---------------------------------------------------------------------------
__global__ void pack_w_kernel(const float* __restrict__ src, int sel, int K)
{
    __half* dst = (sel == 0) ? g_Wih0p : (sel == 1) ? g_Whh0p
                : (sel == 2) ? g_Wih1p : g_Whh1p;
    const int NKP = K >> 5;
    size_t n = (size_t)G4H * K;
    for (size_t idx = (size_t)blockIdx.x * blockDim.x + threadIdx.x; idx < n;
         idx += (size_t)gridDim.x * blockDim.x) {
        int blk = (int)(idx >> 12);         // 4096 halves per block
        int wi  = (int)(idx & 4095);
        int nl = wi >> 5, kl = wi & 31;
        int nt = blk / NKP, kp = blk % NKP;
        int p = nt * 128 + nl;
        int k = kp * 32 + kl;
        int j = p >> 2, g = p & 3;
        dst[idx] = __float2half_rn(src[(size_t)(g * HH + j) * K + k]);
    }
}

__global__ void pack_ctx_kernel(const float* __restrict__ src)
{
    size_t n = (size_t)BB * TT * II;
    for (size_t idx = (size_t)blockIdx.x * blockDim.x + threadIdx.x; idx < n;
         idx += (size_t)gridDim.x * blockDim.x) {
        int blk = (int)(idx >> 11);         // 2048 halves per block
        int wi  = (int)(idx & 2047);
        int r = wi >> 5, kl = wi & 31;
        int mt = blk >> 4, kp = blk & 15;   // NKP = 16
        size_t row = (size_t)mt * 64 + r;
        g_ctxp[idx] = __float2half_rn(src[row * II + kp * 32 + kl]);
    }
}

__global__ void bias_kernel(const float* __restrict__ bih,
                            const float* __restrict__ bhh, int layer)
{
    int p = blockIdx.x * blockDim.x + threadIdx.x;
    if (p < G4H) {
        int j = p >> 2, g = p & 3;
        int r = g * HH + j;
        (layer ? g_b1p : g_b0p)[p] = bih[r] + bhh[r];
    }
}

__global__ void init_hc_kernel(const float* __restrict__ init_hidden)
{
    int i = blockIdx.x * blockDim.x + threadIdx.x;
    if (i < BB * HH) {
        int b = i >> 10, j = i & 1023;
        size_t idx = (size_t)((b >> 6) * 32 + (j >> 5)) * 2048
                   + (b & 63) * 32 + (j & 31);
        g_hA[0][idx] = __float2half_rn(init_hidden[i]);
        g_c[i] = 0.f;
    }
}

// readout: out[b] = h_final[b] . W_ro + b_ro (h from packed fp16 image)
__global__ void readout_kernel(const float* __restrict__ Wro,
                               const float* __restrict__ bro,
                               float* __restrict__ out)
{
    int b = blockIdx.x;
    float s = 0.f;
    for (int j = threadIdx.x; j < HH; j += 128) {
        size_t idx = (size_t)((b >> 6) * 32 + (j >> 5)) * 2048
                   + (b & 63) * 32 + (j & 31);
        s += __half2float(g_hA[0][idx]) * Wro[j];
    }
    #pragma unroll
    for (int o = 16; o; o >>= 1) s += __shfl_down_sync(0xffffffff, s, o);
    __shared__ float red[4];
    if ((threadIdx.x & 31) == 0) red[threadIdx.x >> 5] = s;
    __syncthreads();
    if (threadIdx.x == 0)
        out[b] = red[0] + red[1] + red[2] + red[3] + bro[0];
}

// ---------------------------------------------------------------------------
extern "C" void kernel_launch(void* const* d_in, const int* in_sizes, int n_in,
                              void* d_out, int out_size)
{
    const float* init_hidden = (const float*)d_in[0];
    const float* context     = (const float*)d_in[1];
    const float* W_ih0       = (const float*)d_in[2];
    const float* W_hh0       = (const float*)d_in[3];
    const float* b_ih0       = (const float*)d_in[4];
    const float* b_hh0       = (const float*)d_in[5];
    const float* W_ih1       = (const float*)d_in[6];
    const float* W_hh1       = (const float*)d_in[7];
    const float* b_ih1       = (const float*)d_in[8];
    const float* b_hh1       = (const float*)d_in[9];
    const float* W_ro        = (const float*)d_in[10];
    const float* b_ro        = (const float*)d_in[11];
    float* out = (float*)d_out;

    // ---- preprocessing: pack weights / context (fp16), combine biases ----
    pack_w_kernel<<<2048, 256>>>(W_ih0, 0, II);
    pack_w_kernel<<<2048, 256>>>(W_hh0, 1, HH);
    pack_w_kernel<<<2048, 256>>>(W_ih1, 2, HH);
    pack_w_kernel<<<2048, 256>>>(W_hh1, 3, HH);
    bias_kernel<<<(G4H + 255) / 256, 256>>>(b_ih0, b_hh0, 0);
    bias_kernel<<<(G4H + 255) / 256, 256>>>(b_ih1, b_hh1, 1);
    pack_ctx_kernel<<<4096, 256>>>(context);

    const int  ginit = (BB * HH + 255) / 256;
    const dim3 blk(256);
    const dim3 g_in(32, (BB * TT) / 64);   // (32, 1024)
    const dim3 g_st(32, 4);

    // ---- layer 0 ----
    input_gemm_kernel<<<g_in, blk>>>(0);
    init_hc_kernel<<<ginit, 256>>>(init_hidden);
    for (int t = 0; t < TT; t++)
        lstm_step_kernel<true><<<g_st, blk>>>(0, t, t & 1);

    // ---- layer 1 ----
    input_gemm_kernel<<<g_in, blk>>>(1);
    init_hc_kernel<<<ginit, 256>>>(init_hidden);
    for (int t = 0; t < TT; t++)
        lstm_step_kernel<false><<<g_st, blk>>>(1, t, t & 1);

    // ---- readout ----
    readout_kernel<<<BB, 128>>>(W_ro, b_ro, out);
}

// round 8
// speedup vs baseline: 2.3442x; 1.1524x over previous
#include <cuda_runtime.h>
#include <cuda_fp16.h>
#include <cstdint>

// ---------------------------------------------------------------------------
// FidelityLSTM: 2-layer LSTM (B=256, T=256, I=512, H=1024) + readout.
//
// Round-7: layer-wavefront. Each wave launch i runs concurrently:
//   z=0: layer-0 step t=i        (gates = xg0[:,t] + h1 @ Whh0)
//   z=1: xg1 GEMM for t=i-1      (xg1 = h1_t @ Wih1 + b1)
//   z=2: layer-1 step t=i-2      (gates = xg1[:,t] + h2 @ Whh1)
// All phases are 64x128x1024 CTAs -> 384 CTAs/launch, 258-launch chain
// (vs 512 launches of 128 CTAs + a 274-GMAC batch GEMM before).
// Mainloop: fp16 m16n8k16 mma.sync, 3-stage cp.async, 1 sync/panel,
// __launch_bounds__(256,2) for 2 CTAs/SM.
// ---------------------------------------------------------------------------

#define BB   256
#define TT   256
#define II   512
#define HH   1024
#define G4H  4096

// ------------------------- scratch (device globals) ------------------------
// W blocks: [128 n][32 k] halves, 4096 halves each, index (nt*NKP+kp).
// A blocks: [64 rows][32 k] halves, 2048 halves each, index (mt*NKP+kp).
__device__ __align__(16) __half g_Wih0p[(size_t)G4H * II];
__device__ __align__(16) __half g_Whh0p[(size_t)G4H * HH];
__device__ __align__(16) __half g_Wih1p[(size_t)G4H * HH];
__device__ __align__(16) __half g_Whh1p[(size_t)G4H * HH];
__device__ float g_b0p[G4H];
__device__ float g_b1p[G4H];
__device__ __align__(16) __half g_ctxp[(size_t)BB * TT * II];
__device__ __align__(16) __half g_hA0[2][BB * HH];   // layer-0 h ping-pong
__device__ __align__(16) __half g_hA1[2][BB * HH];   // layer-1 h ping-pong
__device__ float g_c0[BB * HH];
__device__ float g_c1[BB * HH];
__device__ float g_xg0[(size_t)BB * TT * G4H];       // layer-0 input gates
__device__ float g_xg1[2][(size_t)BB * G4H];         // layer-1 xg ping-pong

// ------------------------------ helpers ------------------------------------
__device__ __forceinline__ float sigmoidf_(float x) {
    return 1.f / (1.f + __expf(-x));
}

__device__ __forceinline__ void cpa16(const __half* dst, const __half* src) {
    uint32_t d = (uint32_t)__cvta_generic_to_shared(dst);
    asm volatile("cp.async.cg.shared.global [%0], [%1], 16;\n"
                 :: "r"(d), "l"(src));
}

__device__ __forceinline__ void ldsm4(uint32_t r[4], const __half* p) {
    uint32_t a = (uint32_t)__cvta_generic_to_shared(p);
    asm volatile("ldmatrix.sync.aligned.m8n8.x4.shared.b16 {%0,%1,%2,%3}, [%4];"
                 : "=r"(r[0]), "=r"(r[1]), "=r"(r[2]), "=r"(r[3]) : "r"(a));
}

__device__ __forceinline__ void mma16(float d[4], const uint32_t a[4],
                                      uint32_t b0, uint32_t b1) {
    asm volatile(
        "mma.sync.aligned.m16n8k16.row.col.f32.f16.f16.f32 "
        "{%0,%1,%2,%3}, {%4,%5,%6,%7}, {%8,%9}, {%0,%1,%2,%3};"
        : "+f"(d[0]), "+f"(d[1]), "+f"(d[2]), "+f"(d[3])
        : "r"(a[0]), "r"(a[1]), "r"(a[2]), "r"(a[3]), "r"(b0), "r"(b1));
}

// ---------------------------------------------------------------------------
// GEMM mainloop: C[64 x 128], A blocks [64x32], B blocks [128x32].
// 256 threads, 8 warps = 2(m) x 4(n), warp tile 32x32, mma m16n8k16.
// 3-stage cp.async pipeline, ONE __syncthreads per 32-k panel.
// smem: 3 x (2560 A + 5120 B) halves = 46080 B. Rows padded to 40 halves.
// ---------------------------------------------------------------------------
__device__ __forceinline__ void gemm_fp16(
    const __half* __restrict__ Ablk, const __half* __restrict__ Bblk,
    int NKP, __half* sm, float acc[2][4][4])
{
    const int tid  = threadIdx.x;
    const int lane = tid & 31;
    const int warp = tid >> 5;
    const int wm   = warp >> 2;   // 0..1
    const int wn   = warp & 3;    // 0..3

    const int ar = tid >> 2;            // 0..63
    const int ac = (tid & 3) * 8;       // 0,8,16,24

#define FILL_P(kp, s) do {                                                  \
        const __half* ga = Ablk + (size_t)(kp) * 2048;                      \
        const __half* gb = Bblk + (size_t)(kp) * 4096;                      \
        __half* As_ = sm + (s) * 7680;                                      \
        __half* Bs_ = As_ + 2560;                                           \
        cpa16(As_ + ar * 40 + ac, ga + ar * 32 + ac);                       \
        cpa16(Bs_ + ar * 40 + ac, gb + ar * 32 + ac);                       \
        cpa16(Bs_ + (ar + 64) * 40 + ac, gb + (ar + 64) * 32 + ac);         \
    } while (0)

    FILL_P(0, 0);
    asm volatile("cp.async.commit_group;\n");
    FILL_P(1, 1);
    asm volatile("cp.async.commit_group;\n");

    int s_c = 0, s_f = 2;
    for (int kp = 0; kp < NKP; kp++) {
        asm volatile("cp.async.wait_group 1;\n");
        __syncthreads();
        if (kp + 2 < NKP) FILL_P(kp + 2, s_f);
        asm volatile("cp.async.commit_group;\n");

        __half* Ac = sm + s_c * 7680;
        __half* Bc = Ac + 2560;
        #pragma unroll
        for (int ks = 0; ks < 2; ks++) {
            uint32_t a[2][4];
            #pragma unroll
            for (int mf = 0; mf < 2; mf++) {
                int row = wm * 32 + mf * 16 + (lane & 7) + (lane & 8);
                int col = ks * 16 + ((lane >> 4) & 1) * 8;
                ldsm4(a[mf], Ac + row * 40 + col);
            }
            #pragma unroll
            for (int nfp = 0; nfp < 2; nfp++) {
                int row = wn * 32 + nfp * 16 + (lane & 7) + ((lane & 16) >> 1);
                int col = ks * 16 + (lane & 8);
                uint32_t b[4];
                ldsm4(b, Bc + row * 40 + col);
                mma16(acc[0][nfp * 2],     a[0], b[0], b[1]);
                mma16(acc[1][nfp * 2],     a[1], b[0], b[1]);
                mma16(acc[0][nfp * 2 + 1], a[0], b[2], b[3]);
                mma16(acc[1][nfp * 2 + 1], a[1], b[2], b[3]);
            }
        }
        if (++s_c == 3) s_c = 0;
        if (++s_f == 3) s_f = 0;
    }
    __syncthreads();   // protect smem reuse by epilogue
#undef FILL_P
}

// ---------------------------------------------------------------------------
// LSTM step epilogue: acc + xg -> gates -> cell update -> packed fp16 h.
// smem_f reused as gs[64][132].
// ---------------------------------------------------------------------------
__device__ __forceinline__ void step_epilogue(
    float acc[2][4][4], float* smem_f,
    const float* __restrict__ xrow_base, size_t xrow_stride,
    float* __restrict__ cbuf, __half* __restrict__ hout,
    int m0, int nt)
{
    const int lane = threadIdx.x & 31;
    const int warp = threadIdx.x >> 5;
    const int wm = warp >> 2, wn = warp & 3;
    const int p0 = nt * 128;

    float* gs = smem_f;   // [64][132]
    #pragma unroll
    for (int mf = 0; mf < 2; mf++) {
        int lm = wm * 32 + mf * 16 + (lane >> 2);
        #pragma unroll
        for (int nf = 0; nf < 4; nf++) {
            int lp = wn * 32 + nf * 8 + ((lane & 3) << 1);
            const float* x0 = xrow_base + (size_t)(m0 + lm) * xrow_stride + p0 + lp;
            gs[lm * 132 + lp]     = acc[mf][nf][0] + x0[0];
            gs[lm * 132 + lp + 1] = acc[mf][nf][1] + x0[1];
            const float* x1 = xrow_base + (size_t)(m0 + lm + 8) * xrow_stride + p0 + lp;
            gs[(lm + 8) * 132 + lp]     = acc[mf][nf][2] + x1[0];
            gs[(lm + 8) * 132 + lp + 1] = acc[mf][nf][3] + x1[1];
        }
    }
    __syncthreads();

    const int j0 = p0 >> 2;
    const int mtl = m0 >> 6;
    #pragma unroll
    for (int it = threadIdx.x; it < 64 * 32; it += 256) {
        int lm = it >> 5;
        int lj = it & 31;
        float4 gv = *(float4*)(gs + lm * 132 + (lj << 2));
        int b = m0 + lm;
        int j = j0 + lj;
        float ig = sigmoidf_(gv.x);
        float fg = sigmoidf_(gv.y);
        float gg = tanhf(gv.z);
        float og = sigmoidf_(gv.w);
        int hc = b * HH + j;
        float c = fg * cbuf[hc] + ig * gg;
        cbuf[hc] = c;
        // next-step A image: block (mtl*32 + nt), row lm, k-col lj
        hout[(size_t)(mtl * 32 + nt) * 2048 + lm * 32 + lj] =
            __float2half_rn(og * tanhf(c));
    }
}

// ---------------------------------------------------------------------------
// Wavefront kernel: grid (32, 4, 3), 256 threads.
//   z=0: layer-0 step t=i     z=1: xg1 GEMM t=i-1    z=2: layer-1 step t=i-2
// ---------------------------------------------------------------------------
__global__ void __launch_bounds__(256, 2)
wave_kernel(int i)
{
    __shared__ __align__(16) float smem_f[11520];   // 46080 B
    __half* sm = (__half*)smem_f;

    const int z   = blockIdx.z;
    const int nt  = blockIdx.x;           // 0..31
    const int mtl = blockIdx.y;           // 0..3
    const int m0  = mtl * 64;

    float acc[2][4][4];
    #pragma unroll
    for (int a = 0; a < 2; a++)
        #pragma unroll
        for (int b = 0; b < 4; b++)
            #pragma unroll
            for (int l = 0; l < 4; l++) acc[a][b][l] = 0.f;

    if (z == 0) {
        const int t = i;
        if (t >= TT) return;
        gemm_fp16(g_hA0[t & 1] + (size_t)mtl * 32 * 2048,
                  g_Whh0p + (size_t)nt * 32 * 4096, 32, sm, acc);
        // xg0 rows indexed by global row b*TT + t
        step_epilogue(acc, smem_f,
                      g_xg0 + (size_t)t * G4H, (size_t)TT * G4H,
                      g_c0, g_hA0[(t + 1) & 1], m0, nt);
    } else if (z == 1) {
        const int t = i - 1;
        if (t < 0 || t >= TT) return;
        gemm_fp16(g_hA0[(t + 1) & 1] + (size_t)mtl * 32 * 2048,
                  g_Wih1p + (size_t)nt * 32 * 4096, 32, sm, acc);
        // bias-add epilogue into g_xg1[t&1]
        const int lane = threadIdx.x & 31;
        const int warp = threadIdx.x >> 5;
        const int wm = warp >> 2, wn = warp & 3;
        const int p0 = nt * 128;
        float* dst = g_xg1[t & 1];
        #pragma unroll
        for (int mf = 0; mf < 2; mf++) {
            int gm = m0 + wm * 32 + mf * 16 + (lane >> 2);
            #pragma unroll
            for (int nf = 0; nf < 4; nf++) {
                int gp = p0 + wn * 32 + nf * 8 + ((lane & 3) << 1);
                float b0v = g_b1p[gp], b1v = g_b1p[gp + 1];
                size_t base = (size_t)gm * G4H + gp;
                dst[base]     = acc[mf][nf][0] + b0v;
                dst[base + 1] = acc[mf][nf][1] + b1v;
                size_t base2 = base + (size_t)8 * G4H;
                dst[base2]     = acc[mf][nf][2] + b0v;
                dst[base2 + 1] = acc[mf][nf][3] + b1v;
            }
        }
    } else {
        const int t = i - 2;
        if (t < 0) return;
        gemm_fp16(g_hA1[t & 1] + (size_t)mtl * 32 * 2048,
                  g_Whh1p + (size_t)nt * 32 * 4096, 32, sm, acc);
        step_epilogue(acc, smem_f,
                      g_xg1[t & 1], (size_t)G4H,
                      g_c1, g_hA1[(t + 1) & 1], m0, nt);
    }
}

// ---------------------------------------------------------------------------
// Context input GEMM: xg0[row][p] = ctx @ Wih0^T + b0.  grid (32, 1024).
// ---------------------------------------------------------------------------
__global__ void __launch_bounds__(256, 2)
ctx_gemm_kernel()
{
    __shared__ __align__(16) float smem_f[11520];
    __half* sm = (__half*)smem_f;

    const int nt = blockIdx.x;
    const int mt = blockIdx.y;
    const int p0 = nt * 128;
    const int m0 = mt * 64;

    float acc[2][4][4];
    #pragma unroll
    for (int a = 0; a < 2; a++)
        #pragma unroll
        for (int b = 0; b < 4; b++)
            #pragma unroll
            for (int l = 0; l < 4; l++) acc[a][b][l] = 0.f;

    gemm_fp16(g_ctxp + (size_t)mt * 16 * 2048,
              g_Wih0p + (size_t)nt * 16 * 4096, 16, sm, acc);

    const int lane = threadIdx.x & 31;
    const int warp = threadIdx.x >> 5;
    const int wm = warp >> 2, wn = warp & 3;

    #pragma unroll
    for (int mf = 0; mf < 2; mf++) {
        int gm = m0 + wm * 32 + mf * 16 + (lane >> 2);
        #pragma unroll
        for (int nf = 0; nf < 4; nf++) {
            int gp = p0 + wn * 32 + nf * 8 + ((lane & 3) << 1);
            float b0v = g_b0p[gp], b1v = g_b0p[gp + 1];
            size_t base = (size_t)gm * G4H + gp;
            g_xg0[base]     = acc[mf][nf][0] + b0v;
            g_xg0[base + 1] = acc[mf][nf][1] + b1v;
            size_t base2 = base + (size_t)8 * G4H;
            g_xg0[base2]     = acc[mf][nf][2] + b0v;
            g_xg0[base2 + 1] = acc[mf][nf][3] + b1v;
        }
    }
}

// ---------------------------------------------------------------------------
// Packing kernels (fp32 -> fp16 RN, gate-interleaved p = 4j+g, blocked)
// ---------------------------------------------------------------------------
__global__ void pack_w_kernel(const float* __restrict__ src, int sel, int K)
{
    __half* dst = (sel == 0) ? g_Wih0p : (sel == 1) ? g_Whh0p
                : (sel == 2) ? g_Wih1p : g_Whh1p;
    const int NKP = K >> 5;
    size_t n = (size_t)G4H * K;
    for (size_t idx = (size_t)blockIdx.x * blockDim.x + threadIdx.x; idx < n;
         idx += (size_t)gridDim.x * blockDim.x) {
        int blk = (int)(idx >> 12);
        int wi  = (int)(idx & 4095);
        int nl = wi >> 5, kl = wi & 31;
        int nt = blk / NKP, kp = blk % NKP;
        int p = nt * 128 + nl;
        int k = kp * 32 + kl;
        int j = p >> 2, g = p & 3;
        dst[idx] = __float2half_rn(src[(size_t)(g * HH + j) * K + k]);
    }
}

__global__ void pack_ctx_kernel(const float* __restrict__ src)
{
    size_t n = (size_t)BB * TT * II;
    for (size_t idx = (size_t)blockIdx.x * blockDim.x + threadIdx.x; idx < n;
         idx += (size_t)gridDim.x * blockDim.x) {
        int blk = (int)(idx >> 11);
        int wi  = (int)(idx & 2047);
        int r = wi >> 5, kl = wi & 31;
        int mt = blk >> 4, kp = blk & 15;
        size_t row = (size_t)mt * 64 + r;
        g_ctxp[idx] = __float2half_rn(src[row * II + kp * 32 + kl]);
    }
}

__global__ void bias_kernel(const float* __restrict__ bih,
                            const float* __restrict__ bhh, int layer)
{
    int p = blockIdx.x * blockDim.x + threadIdx.x;
    if (p < G4H) {
        int j = p >> 2, g = p & 3;
        int r = g * HH + j;
        (layer ? g_b1p : g_b0p)[p] = bih[r] + bhh[r];
    }
}

__global__ void init_hc_kernel(const float* __restrict__ init_hidden)
{
    int i = blockIdx.x * blockDim.x + threadIdx.x;
    if (i < BB * HH) {
        int b = i >> 10, j = i & 1023;
        size_t idx = (size_t)((b >> 6) * 32 + (j >> 5)) * 2048
                   + (b & 63) * 32 + (j & 31);
        __half hv = __float2half_rn(init_hidden[i]);
        g_hA0[0][idx] = hv;
        g_hA1[0][idx] = hv;
        g_c0[i] = 0.f;
        g_c1[i] = 0.f;
    }
}

// readout: out[b] = h2_final[b] . W_ro + b_ro   (h2 final in g_hA1[0])
__global__ void readout_kernel(const float* __restrict__ Wro,
                               const float* __restrict__ bro,
                               float* __restrict__ out)
{
    int b = blockIdx.x;
    float s = 0.f;
    for (int j = threadIdx.x; j < HH; j += 128) {
        size_t idx = (size_t)((b >> 6) * 32 + (j >> 5)) * 2048
                   + (b & 63) * 32 + (j & 31);
        s += __half2float(g_hA1[0][idx]) * Wro[j];
    }
    #pragma unroll
    for (int o = 16; o; o >>= 1) s += __shfl_down_sync(0xffffffff, s, o);
    __shared__ float red[4];
    if ((threadIdx.x & 31) == 0) red[threadIdx.x >> 5] = s;
    __syncthreads();
    if (threadIdx.x == 0)
        out[b] = red[0] + red[1] + red[2] + red[3] + bro[0];
}

// ---------------------------------------------------------------------------
extern "C" void kernel_launch(void* const* d_in, const int* in_sizes, int n_in,
                              void* d_out, int out_size)
{
    const float* init_hidden = (const float*)d_in[0];
    const float* context     = (const float*)d_in[1];
    const float* W_ih0       = (const float*)d_in[2];
    const float* W_hh0       = (const float*)d_in[3];
    const float* b_ih0       = (const float*)d_in[4];
    const float* b_hh0       = (const float*)d_in[5];
    const float* W_ih1       = (const float*)d_in[6];
    const float* W_hh1       = (const float*)d_in[7];
    const float* b_ih1       = (const float*)d_in[8];
    const float* b_hh1       = (const float*)d_in[9];
    const float* W_ro        = (const float*)d_in[10];
    const float* b_ro        = (const float*)d_in[11];
    float* out = (float*)d_out;

    // ---- preprocessing ----
    pack_w_kernel<<<2048, 256>>>(W_ih0, 0, II);
    pack_w_kernel<<<2048, 256>>>(W_hh0, 1, HH);
    pack_w_kernel<<<2048, 256>>>(W_ih1, 2, HH);
    pack_w_kernel<<<2048, 256>>>(W_hh1, 3, HH);
    bias_kernel<<<(G4H + 255) / 256, 256>>>(b_ih0, b_hh0, 0);
    bias_kernel<<<(G4H + 255) / 256, 256>>>(b_ih1, b_hh1, 1);
    pack_ctx_kernel<<<4096, 256>>>(context);

    // ---- layer-0 input gates (big parallel GEMM) ----
    ctx_gemm_kernel<<<dim3(32, (BB * TT) / 64), 256>>>();
    init_hc_kernel<<<(BB * HH + 255) / 256, 256>>>(init_hidden);

    // ---- wavefront: 258 launches cover both layers' recurrences ----
    const dim3 g_wave(32, 4, 3);
    for (int i = 0; i < TT + 2; i++)
        wave_kernel<<<g_wave, 256>>>(i);

    // ---- readout ----
    readout_kernel<<<BB, 128>>>(W_ro, b_ro, out);
}